// round 15
// baseline (speedup 1.0000x reference)
#include <cuda_runtime.h>
#include <cuda_bf16.h>
#include <math.h>
#include <stdint.h>

// ---------------------------------------------------------------------------
// LLaMA attention block (sm_103 non-'a' ISA: mma.sync + ldmatrix + cp.async).
// R14 (validated 2175us) + flash exp2 folding + rescale-skip.
// GEMMs: bf16x2 split MMA, 2-stage cp.async pipeline, fused epilogues.
// Attention: bf16x2 split FA2, BQ=128, pipelined K/V, heavy-first ordering.
// Logits are pre-scaled by log2(e) in the Q-projection epilogue; flash uses
// exp2f throughout (identical softmax).
// ---------------------------------------------------------------------------

#define T_SEQ   2048
#define D_MODEL 4096
#define KV_DIM  1024
#define KV2     2048
#define N_HEADS 32
#define HD      128
#define SCALE   0.08838834764831845f   // 1/sqrt(128)
#define LOG2E   1.4426950408889634f

#define SZ_X    (T_SEQ * D_MODEL)
#define SZ_WQ   (D_MODEL * D_MODEL)
#define SZ_WK   (D_MODEL * KV_DIM)
#define SZ_KV2  (T_SEQ * KV2)

// bf16 hi/lo scratch (weights TRANSPOSED: [N][K]; wkv concatenated on N)
__device__ __nv_bfloat16 g_xh  [SZ_X],   g_xl  [SZ_X];
__device__ __nv_bfloat16 g_aoh [SZ_X],   g_aol [SZ_X];
__device__ __nv_bfloat16 g_wqh [SZ_WQ],  g_wql [SZ_WQ];
__device__ __nv_bfloat16 g_wkvh[2*SZ_WK],g_wkvl[2*SZ_WK];
__device__ __nv_bfloat16 g_woh [SZ_WQ],  g_wol [SZ_WQ];
// attention operands, hi/lo (written by fused GEMM epilogues)
__device__ __nv_bfloat16 g_Qh [SZ_X],   g_Ql [SZ_X];
__device__ __nv_bfloat16 g_KVh[SZ_KV2], g_KVl[SZ_KV2];
// rope tables (fp64-built)
__device__ float g_ct[T_SEQ * 64];
__device__ float g_st[T_SEQ * 64];

// ---------------------------------------------------------------------------
// helpers
// ---------------------------------------------------------------------------
__device__ __forceinline__ uint32_t s2u(const void* p) {
    return (uint32_t)__cvta_generic_to_shared(p);
}
__device__ __forceinline__ void ldmx4(uint32_t& r0, uint32_t& r1,
                                      uint32_t& r2, uint32_t& r3, uint32_t a) {
    asm volatile("ldmatrix.sync.aligned.m8n8.x4.shared.b16 {%0,%1,%2,%3},[%4];\n"
                 : "=r"(r0), "=r"(r1), "=r"(r2), "=r"(r3) : "r"(a));
}
__device__ __forceinline__ void ldmx4t(uint32_t& r0, uint32_t& r1,
                                       uint32_t& r2, uint32_t& r3, uint32_t a) {
    asm volatile("ldmatrix.sync.aligned.m8n8.x4.trans.shared.b16 {%0,%1,%2,%3},[%4];\n"
                 : "=r"(r0), "=r"(r1), "=r"(r2), "=r"(r3) : "r"(a));
}
__device__ __forceinline__ void mma16816(float* d, uint32_t a0, uint32_t a1,
                                         uint32_t a2, uint32_t a3,
                                         uint32_t b0, uint32_t b1) {
    asm volatile(
        "mma.sync.aligned.m16n8k16.row.col.f32.bf16.bf16.f32 "
        "{%0,%1,%2,%3},{%4,%5,%6,%7},{%8,%9},{%0,%1,%2,%3};\n"
        : "+f"(d[0]), "+f"(d[1]), "+f"(d[2]), "+f"(d[3])
        : "r"(a0), "r"(a1), "r"(a2), "r"(a3), "r"(b0), "r"(b1));
}
__device__ __forceinline__ void split_hl(float v, __nv_bfloat16& h, __nv_bfloat16& l) {
    h = __float2bfloat16(v);
    l = __float2bfloat16(v - __bfloat162float(h));
}
__device__ __forceinline__ uint32_t pack_hl(float a, float b, uint32_t& lo) {
    __nv_bfloat16 ha, la, hb, lb;
    split_hl(a, ha, la);
    split_hl(b, hb, lb);
    __nv_bfloat162 H; H.x = ha; H.y = hb;
    __nv_bfloat162 L; L.x = la; L.y = lb;
    lo = *(uint32_t*)&L;
    return *(uint32_t*)&H;
}
__device__ __forceinline__ void cpa16(uint32_t s, const void* g) {
    asm volatile("cp.async.cg.shared.global [%0], [%1], 16;" :: "r"(s), "l"(g));
}

// ---------------------------------------------------------------------------
// rope tables (fp64 trig, computed once)
// ---------------------------------------------------------------------------
__global__ void rope_tab(float* __restrict__ ct, float* __restrict__ st)
{
    const int t = blockIdx.x;
    const int j = threadIdx.x;           // 64 threads
    const double fj = pow(10000.0, -(double)j / 64.0);
    const double a  = (double)t * fj;
    ct[t * 64 + j] = (float)cos(a);
    st[t * 64 + j] = (float)sin(a);
}

// ---------------------------------------------------------------------------
// fp32 -> bf16 hi/lo, 8 elems/thread
// ---------------------------------------------------------------------------
__global__ __launch_bounds__(256)
void conv_hilo8(const float* __restrict__ s, __nv_bfloat16* __restrict__ h,
                __nv_bfloat16* __restrict__ l, int n)
{
    int i = (blockIdx.x * blockDim.x + threadIdx.x) * 8;
    if (i >= n) return;
    float4 v0 = *(const float4*)(s + i);
    float4 v1 = *(const float4*)(s + i + 4);
    __nv_bfloat16 hh[8], ll[8];
    split_hl(v0.x, hh[0], ll[0]); split_hl(v0.y, hh[1], ll[1]);
    split_hl(v0.z, hh[2], ll[2]); split_hl(v0.w, hh[3], ll[3]);
    split_hl(v1.x, hh[4], ll[4]); split_hl(v1.y, hh[5], ll[5]);
    split_hl(v1.z, hh[6], ll[6]); split_hl(v1.w, hh[7], ll[7]);
    *(uint4*)(h + i) = *(uint4*)hh;
    *(uint4*)(l + i) = *(uint4*)ll;
}

// ---------------------------------------------------------------------------
// conversion + transpose: W [K,N] fp32 -> Wt hi/lo [N,K] bf16 (validated)
// ---------------------------------------------------------------------------
__global__ __launch_bounds__(256)
void conv_t(const float* __restrict__ w, __nv_bfloat16* __restrict__ th,
            __nv_bfloat16* __restrict__ tl, int K, int N)
{
    __shared__ float tile[32][33];
    const int n0 = blockIdx.x * 32, k0 = blockIdx.y * 32;
    const int tx = threadIdx.x, ty = threadIdx.y;
#pragma unroll
    for (int i = 0; i < 4; i++)
        tile[ty + 8 * i][tx] = w[(size_t)(k0 + ty + 8 * i) * N + n0 + tx];
    __syncthreads();
#pragma unroll
    for (int i = 0; i < 4; i++) {
        float v = tile[tx][ty + 8 * i];
        __nv_bfloat16 h, l;
        split_hl(v, h, l);
        size_t o = (size_t)(n0 + ty + 8 * i) * K + k0 + tx;
        th[o] = h;
        tl[o] = l;
    }
}

// ---------------------------------------------------------------------------
// bf16x2-split MMA GEMM, 2-stage cp.async pipeline, templated epilogue.
// MODE 0: C fp32.  MODE 1: rope(+scale)+split -> Dh/Dl bf16 (rope iff
// n0 < rope_limit).
// ---------------------------------------------------------------------------
#define GP_MATE 5120
#define GP_STGE (4 * GP_MATE)
#define GP_SMEM (2 * GP_STGE * 2)

template<int MODE>
__global__ __launch_bounds__(256)
void gemm_pipe(const __nv_bfloat16* __restrict__ Ah, const __nv_bfloat16* __restrict__ Al,
               const __nv_bfloat16* __restrict__ Bh, const __nv_bfloat16* __restrict__ Bl,
               float* __restrict__ C,
               __nv_bfloat16* __restrict__ Dh, __nv_bfloat16* __restrict__ Dl,
               const float* __restrict__ ctab, const float* __restrict__ stab,
               int M, int N, int K, int dstride, float scale, int rope_limit)
{
    extern __shared__ __nv_bfloat16 smg[];
    const uint32_t smbase = s2u(smg);

    const int tid  = threadIdx.x;
    const int lane = tid & 31;
    const int wid  = tid >> 5;
    const int m0 = blockIdx.y * 128, n0 = blockIdx.x * 128;
    const int wm = (wid & 1) * 64;
    const int wn = (wid >> 1) * 32;

    const int r0 = tid >> 2;
    const int o0 = (tid & 3) * 8;
    const int r1 = r0 + 64;

    float acc[4][4][4];
#pragma unroll
    for (int a = 0; a < 4; a++)
#pragma unroll
        for (int b = 0; b < 4; b++)
#pragma unroll
            for (int c = 0; c < 4; c++) acc[a][b][c] = 0.f;

    const int a_row = ((lane >> 3) & 1) * 8 + (lane & 7);
    const int a_col = (lane >> 4) * 8;
    const int b_row = ((lane >> 4) & 1) * 8 + (lane & 7);
    const int b_col = ((lane >> 3) & 1) * 8;

    const int NI = K / 32;

#define GP_ISSUE(st, kk0)                                                       \
    do {                                                                        \
        const uint32_t sb = smbase + (st) * (GP_STGE * 2);                      \
        cpa16(sb + (r0 * 40 + o0) * 2, Ah + (size_t)(m0 + r0) * K + (kk0) + o0);\
        cpa16(sb + (r1 * 40 + o0) * 2, Ah + (size_t)(m0 + r1) * K + (kk0) + o0);\
        cpa16(sb + (GP_MATE + r0 * 40 + o0) * 2,                                \
              Al + (size_t)(m0 + r0) * K + (kk0) + o0);                         \
        cpa16(sb + (GP_MATE + r1 * 40 + o0) * 2,                                \
              Al + (size_t)(m0 + r1) * K + (kk0) + o0);                         \
        cpa16(sb + (2 * GP_MATE + r0 * 40 + o0) * 2,                            \
              Bh + (size_t)(n0 + r0) * K + (kk0) + o0);                         \
        cpa16(sb + (2 * GP_MATE + r1 * 40 + o0) * 2,                            \
              Bh + (size_t)(n0 + r1) * K + (kk0) + o0);                         \
        cpa16(sb + (3 * GP_MATE + r0 * 40 + o0) * 2,                            \
              Bl + (size_t)(n0 + r0) * K + (kk0) + o0);                         \
        cpa16(sb + (3 * GP_MATE + r1 * 40 + o0) * 2,                            \
              Bl + (size_t)(n0 + r1) * K + (kk0) + o0);                         \
        asm volatile("cp.async.commit_group;");                                 \
    } while (0)

    GP_ISSUE(0, 0);

    for (int it = 0; it < NI; it++) {
        const int st = it & 1;
        if (it + 1 < NI) {
            GP_ISSUE(it & 1 ? 0 : 1, (it + 1) * 32);
            asm volatile("cp.async.wait_group 1;");
        } else {
            asm volatile("cp.async.wait_group 0;");
        }
        __syncthreads();

        const __nv_bfloat16* pAh = smg + st * GP_STGE;
        const __nv_bfloat16* pAl = pAh + GP_MATE;
        const __nv_bfloat16* pBh = pAh + 2 * GP_MATE;
        const __nv_bfloat16* pBl = pAh + 3 * GP_MATE;

#pragma unroll
        for (int kk = 0; kk < 32; kk += 16) {
            uint32_t ah[4][4], al[4][4], bh[4][2], bl[4][2];
#pragma unroll
            for (int mi = 0; mi < 4; mi++) {
                ldmx4(ah[mi][0], ah[mi][1], ah[mi][2], ah[mi][3],
                      s2u(pAh + (wm + 16 * mi + a_row) * 40 + kk + a_col));
                ldmx4(al[mi][0], al[mi][1], al[mi][2], al[mi][3],
                      s2u(pAl + (wm + 16 * mi + a_row) * 40 + kk + a_col));
            }
#pragma unroll
            for (int nj = 0; nj < 2; nj++) {
                uint32_t t0, t1, t2, t3;
                ldmx4(t0, t1, t2, t3,
                      s2u(pBh + (wn + 16 * nj + b_row) * 40 + kk + b_col));
                bh[2 * nj][0] = t0; bh[2 * nj][1] = t1;
                bh[2 * nj + 1][0] = t2; bh[2 * nj + 1][1] = t3;
                ldmx4(t0, t1, t2, t3,
                      s2u(pBl + (wn + 16 * nj + b_row) * 40 + kk + b_col));
                bl[2 * nj][0] = t0; bl[2 * nj][1] = t1;
                bl[2 * nj + 1][0] = t2; bl[2 * nj + 1][1] = t3;
            }
#pragma unroll
            for (int mi = 0; mi < 4; mi++)
#pragma unroll
                for (int ni = 0; ni < 4; ni++) {
                    mma16816(acc[mi][ni], ah[mi][0], ah[mi][1], ah[mi][2], ah[mi][3],
                             bh[ni][0], bh[ni][1]);
                    mma16816(acc[mi][ni], ah[mi][0], ah[mi][1], ah[mi][2], ah[mi][3],
                             bl[ni][0], bl[ni][1]);
                    mma16816(acc[mi][ni], al[mi][0], al[mi][1], al[mi][2], al[mi][3],
                             bh[ni][0], bh[ni][1]);
                }
        }
        __syncthreads();
    }
#undef GP_ISSUE

    const int g  = lane >> 2;
    const int t2 = (lane & 3) * 2;

    if (MODE == 0) {
#pragma unroll
        for (int mi = 0; mi < 4; mi++)
#pragma unroll
            for (int ni = 0; ni < 4; ni++) {
                const int row = m0 + wm + 16 * mi + g;
                const int col = n0 + wn + 8 * ni + t2;
                *(float2*)&C[(size_t)row * N + col] =
                    make_float2(acc[mi][ni][0], acc[mi][ni][1]);
                *(float2*)&C[(size_t)(row + 8) * N + col] =
                    make_float2(acc[mi][ni][2], acc[mi][ni][3]);
            }
    } else {
        // stage fp32 tile to smem (stride 132), then rope+scale+split
        float* ft = (float*)smg;
        __syncthreads();
#pragma unroll
        for (int mi = 0; mi < 4; mi++)
#pragma unroll
            for (int ni = 0; ni < 4; ni++) {
                const int rr = wm + 16 * mi + g;
                const int cc = wn + 8 * ni + t2;
                ft[rr * 132 + cc]           = acc[mi][ni][0];
                ft[rr * 132 + cc + 1]       = acc[mi][ni][1];
                ft[(rr + 8) * 132 + cc]     = acc[mi][ni][2];
                ft[(rr + 8) * 132 + cc + 1] = acc[mi][ni][3];
            }
        __syncthreads();

        const int r  = tid >> 1;           // 0..127
        const int jh = (tid & 1) * 32;     // 0 or 32
        const int t  = m0 + r;             // sequence position
        const bool dorope = (n0 < rope_limit);
        const float* crow = ctab + t * 64;
        const float* srow = stab + t * 64;

#pragma unroll
        for (int blk = 0; blk < 4; blk++) {
            __nv_bfloat16 h0[8], l0[8], h1[8], l1[8];
#pragma unroll
            for (int jj = 0; jj < 8; jj++) {
                const int j = jh + blk * 8 + jj;
                float a = ft[r * 132 + j];
                float b = ft[r * 132 + j + 64];
                float na, nb;
                if (dorope) {
                    const float c = crow[j], s = srow[j];
                    na = a * c - b * s;
                    nb = b * c + a * s;
                } else { na = a; nb = b; }
                na *= scale; nb *= scale;
                split_hl(na, h0[jj], l0[jj]);
                split_hl(nb, h1[jj], l1[jj]);
            }
            const size_t base = (size_t)t * dstride + n0 + jh + blk * 8;
            *(uint4*)(Dh + base)      = *(uint4*)h0;
            *(uint4*)(Dl + base)      = *(uint4*)l0;
            *(uint4*)(Dh + base + 64) = *(uint4*)h1;
            *(uint4*)(Dl + base + 64) = *(uint4*)l1;
        }
    }
}

// ---------------------------------------------------------------------------
// Flash attention FA2, bf16x2 split, BQ=128, pipelined K/V, bf16 hi/lo out.
// Heavy-first CTA ordering.  Logits pre-scaled by log2(e): exp2f softmax.
// ---------------------------------------------------------------------------
#define FST  136
#define QT   (128 * FST)
#define KVT  (64 * FST)
#define F3_SMEM ((2 * QT + 8 * KVT) * 2)
#define NB   (T_SEQ / 128)

__global__ __launch_bounds__(256)
void flash3(const __nv_bfloat16* __restrict__ Qh, const __nv_bfloat16* __restrict__ Ql,
            const __nv_bfloat16* __restrict__ KVh, const __nv_bfloat16* __restrict__ KVl,
            __nv_bfloat16* __restrict__ AOh, __nv_bfloat16* __restrict__ AOl)
{
    extern __shared__ __nv_bfloat16 smf[];
    __nv_bfloat16* sQh = smf;
    __nv_bfloat16* sQl = sQh + QT;
    __nv_bfloat16* sKV = sQl + QT;
    const uint32_t kvbase = s2u(sKV);

    const int tid  = threadIdx.x;
    const int lane = tid & 31;
    const int wid  = tid >> 5;
    const int wm   = wid * 16;
    const int qb   = NB - 1 - blockIdx.x;   // heavy-first ordering
    const int h    = blockIdx.y;
    const int kh   = h >> 2;

    const int a_row = ((lane >> 3) & 1) * 8 + (lane & 7);
    const int a_col = (lane >> 4) * 8;
    const int b_row = ((lane >> 4) & 1) * 8 + (lane & 7);
    const int b_col = ((lane >> 3) & 1) * 8;
    const int v_row = lane & 15;
    const int v_col = (lane >> 4) * 8;
    const int g     = lane >> 2;
    const int t2    = (lane & 3) * 2;

    const int qr = tid >> 1;
    const int qc = (tid & 1) * 64;
    {
        const __nv_bfloat16* gq0 = Qh + (size_t)(qb * 128 + qr) * D_MODEL + h * HD + qc;
        const __nv_bfloat16* gq1 = Ql + (size_t)(qb * 128 + qr) * D_MODEL + h * HD + qc;
#pragma unroll
        for (int i = 0; i < 8; i++) {
            *(uint4*)&sQh[qr * FST + qc + i * 8] = *(const uint4*)(gq0 + i * 8);
            *(uint4*)&sQl[qr * FST + qc + i * 8] = *(const uint4*)(gq1 + i * 8);
        }
    }

    const int kr = tid >> 2;
    const int kc = (tid & 3) * 32;
    const int ntiles = 2 * qb + 2;

#define F3_ISSUE(jtv)                                                            \
    do {                                                                         \
        const int _st = (jtv) & 1;                                               \
        const int _j0 = (jtv) * 64;                                              \
        const uint32_t sb = kvbase + _st * (4 * KVT) * 2;                        \
        const __nv_bfloat16* khg = KVh + (size_t)(_j0 + kr) * KV2 + kh * HD + kc;\
        const __nv_bfloat16* klg = KVl + (size_t)(_j0 + kr) * KV2 + kh * HD + kc;\
        const __nv_bfloat16* vhg = khg + KV_DIM;                                 \
        const __nv_bfloat16* vlg = klg + KV_DIM;                                 \
        _Pragma("unroll")                                                        \
        for (int i = 0; i < 4; i++) {                                            \
            const uint32_t so = (kr * FST + kc + i * 8) * 2;                     \
            cpa16(sb + so,               khg + i * 8);                           \
            cpa16(sb + KVT * 2 + so,     klg + i * 8);                           \
            cpa16(sb + 2 * KVT * 2 + so, vhg + i * 8);                           \
            cpa16(sb + 3 * KVT * 2 + so, vlg + i * 8);                           \
        }                                                                        \
        asm volatile("cp.async.commit_group;");                                  \
    } while (0)

    float o[16][4];
#pragma unroll
    for (int i = 0; i < 16; i++)
#pragma unroll
        for (int j = 0; j < 4; j++) o[i][j] = 0.f;
    float m0r = -1e30f, m1r = -1e30f, l0r = 0.f, l1r = 0.f;

    F3_ISSUE(0);

    for (int jt = 0; jt < ntiles; jt++) {
        const int st = jt & 1;
        const int j0 = jt * 64;
        if (jt + 1 < ntiles) {
            F3_ISSUE(jt + 1);
            asm volatile("cp.async.wait_group 1;");
        } else {
            asm volatile("cp.async.wait_group 0;");
        }
        __syncthreads();

        const __nv_bfloat16* sKh = sKV + st * 4 * KVT;
        const __nv_bfloat16* sKl = sKh + KVT;
        const __nv_bfloat16* sVh = sKh + 2 * KVT;
        const __nv_bfloat16* sVl = sKh + 3 * KVT;

        float sa[8][4];
#pragma unroll
        for (int c = 0; c < 8; c++)
#pragma unroll
            for (int j = 0; j < 4; j++) sa[c][j] = 0.f;

#pragma unroll
        for (int kk = 0; kk < 8; kk++) {
            uint32_t qh0, qh1, qh2, qh3, ql0, ql1, ql2, ql3;
            ldmx4(qh0, qh1, qh2, qh3, s2u(&sQh[(wm + a_row) * FST + kk * 16 + a_col]));
            ldmx4(ql0, ql1, ql2, ql3, s2u(&sQl[(wm + a_row) * FST + kk * 16 + a_col]));
#pragma unroll
            for (int njp = 0; njp < 4; njp++) {
                uint32_t bh0, bh1, bh2, bh3, bl0, bl1, bl2, bl3;
                ldmx4(bh0, bh1, bh2, bh3,
                      s2u(sKh + (njp * 16 + b_row) * FST + kk * 16 + b_col));
                ldmx4(bl0, bl1, bl2, bl3,
                      s2u(sKl + (njp * 16 + b_row) * FST + kk * 16 + b_col));
                mma16816(sa[2 * njp], qh0, qh1, qh2, qh3, bh0, bh1);
                mma16816(sa[2 * njp], qh0, qh1, qh2, qh3, bl0, bl1);
                mma16816(sa[2 * njp], ql0, ql1, ql2, ql3, bh0, bh1);
                mma16816(sa[2 * njp + 1], qh0, qh1, qh2, qh3, bh2, bh3);
                mma16816(sa[2 * njp + 1], qh0, qh1, qh2, qh3, bl2, bl3);
                mma16816(sa[2 * njp + 1], ql0, ql1, ql2, ql3, bh2, bh3);
            }
        }

        if (jt >= ntiles - 2) {
            const int qr0 = qb * 128 + wm + g;
            const int qr1 = qr0 + 8;
#pragma unroll
            for (int c = 0; c < 8; c++) {
                const int col = j0 + c * 8 + t2;
                if (col     > qr0) sa[c][0] = -1e30f;
                if (col + 1 > qr0) sa[c][1] = -1e30f;
                if (col     > qr1) sa[c][2] = -1e30f;
                if (col + 1 > qr1) sa[c][3] = -1e30f;
            }
        }

        float rm0 = -1e30f, rm1 = -1e30f;
#pragma unroll
        for (int c = 0; c < 8; c++) {
            rm0 = fmaxf(rm0, fmaxf(sa[c][0], sa[c][1]));
            rm1 = fmaxf(rm1, fmaxf(sa[c][2], sa[c][3]));
        }
        rm0 = fmaxf(rm0, __shfl_xor_sync(0xffffffffu, rm0, 1));
        rm0 = fmaxf(rm0, __shfl_xor_sync(0xffffffffu, rm0, 2));
        rm1 = fmaxf(rm1, __shfl_xor_sync(0xffffffffu, rm1, 1));
        rm1 = fmaxf(rm1, __shfl_xor_sync(0xffffffffu, rm1, 2));

        const float mn0 = fmaxf(m0r, rm0);
        const float mn1 = fmaxf(m1r, rm1);

        // rescale O only when the running max changed (exp2 domain)
        if (mn0 != m0r || mn1 != m1r) {
            const float al0 = exp2f(m0r - mn0);
            const float al1 = exp2f(m1r - mn1);
            l0r *= al0;
            l1r *= al1;
#pragma unroll
            for (int dj = 0; dj < 16; dj++) {
                o[dj][0] *= al0;
                o[dj][1] *= al0;
                o[dj][2] *= al1;
                o[dj][3] *= al1;
            }
            m0r = mn0;
            m1r = mn1;
        }

        float rs0 = 0.f, rs1 = 0.f;
#pragma unroll
        for (int c = 0; c < 8; c++) {
            sa[c][0] = exp2f(sa[c][0] - m0r);
            sa[c][1] = exp2f(sa[c][1] - m0r);
            sa[c][2] = exp2f(sa[c][2] - m1r);
            sa[c][3] = exp2f(sa[c][3] - m1r);
            rs0 += sa[c][0] + sa[c][1];
            rs1 += sa[c][2] + sa[c][3];
        }
        rs0 += __shfl_xor_sync(0xffffffffu, rs0, 1);
        rs0 += __shfl_xor_sync(0xffffffffu, rs0, 2);
        rs1 += __shfl_xor_sync(0xffffffffu, rs1, 1);
        rs1 += __shfl_xor_sync(0xffffffffu, rs1, 2);

        l0r += rs0;
        l1r += rs1;

#pragma unroll
        for (int ks = 0; ks < 4; ks++) {
            const int c0 = 2 * ks, c1 = 2 * ks + 1;
            uint32_t pl0, pl1, pl2, pl3;
            const uint32_t ph0 = pack_hl(sa[c0][0], sa[c0][1], pl0);
            const uint32_t ph1 = pack_hl(sa[c0][2], sa[c0][3], pl1);
            const uint32_t ph2 = pack_hl(sa[c1][0], sa[c1][1], pl2);
            const uint32_t ph3 = pack_hl(sa[c1][2], sa[c1][3], pl3);
#pragma unroll
            for (int djp = 0; djp < 8; djp++) {
                uint32_t vh0, vh1, vh2, vh3, vl0, vl1, vl2, vl3;
                ldmx4t(vh0, vh1, vh2, vh3,
                       s2u(sVh + (ks * 16 + v_row) * FST + djp * 16 + v_col));
                ldmx4t(vl0, vl1, vl2, vl3,
                       s2u(sVl + (ks * 16 + v_row) * FST + djp * 16 + v_col));
                mma16816(o[2 * djp], ph0, ph1, ph2, ph3, vh0, vh1);
                mma16816(o[2 * djp], ph0, ph1, ph2, ph3, vl0, vl1);
                mma16816(o[2 * djp], pl0, pl1, pl2, pl3, vh0, vh1);
                mma16816(o[2 * djp + 1], ph0, ph1, ph2, ph3, vh2, vh3);
                mma16816(o[2 * djp + 1], ph0, ph1, ph2, ph3, vl2, vl3);
                mma16816(o[2 * djp + 1], pl0, pl1, pl2, pl3, vh2, vh3);
            }
        }
        __syncthreads();
    }
#undef F3_ISSUE

    // epilogue: normalize + hi/lo split directly to bf16
    const float inv0 = 1.0f / l0r;
    const float inv1 = 1.0f / l1r;
    const int row0 = qb * 128 + wm + g;
    const int row1 = row0 + 8;
#pragma unroll
    for (int dj = 0; dj < 16; dj++) {
        uint32_t lo;
        uint32_t hi = pack_hl(o[dj][0] * inv0, o[dj][1] * inv0, lo);
        const size_t b0 = (size_t)row0 * D_MODEL + h * HD + dj * 8 + t2;
        *(uint32_t*)(AOh + b0) = hi;
        *(uint32_t*)(AOl + b0) = lo;
        hi = pack_hl(o[dj][2] * inv1, o[dj][3] * inv1, lo);
        const size_t b1 = (size_t)row1 * D_MODEL + h * HD + dj * 8 + t2;
        *(uint32_t*)(AOh + b1) = hi;
        *(uint32_t*)(AOl + b1) = lo;
    }
}

// ---------------------------------------------------------------------------
// launch — signature order: x, wq, wk, wv, wo
// ---------------------------------------------------------------------------
extern "C" void kernel_launch(void* const* d_in, const int* in_sizes, int n_in,
                              void* d_out, int out_size)
{
    const float* x  = (const float*)d_in[0];
    const float* wq = (const float*)d_in[1];
    const float* wk = (const float*)d_in[2];
    const float* wv = (const float*)d_in[3];
    const float* wo = (const float*)d_in[4];
    float* out = (float*)d_out;

    __nv_bfloat16 *xh, *xl, *aoh, *aol, *wqh, *wql, *wkvh, *wkvl, *woh, *wol;
    __nv_bfloat16 *qhh, *qll, *kvh, *kvl;
    float *ct, *st;
    cudaGetSymbolAddress((void**)&xh,   g_xh);   cudaGetSymbolAddress((void**)&xl,   g_xl);
    cudaGetSymbolAddress((void**)&aoh,  g_aoh);  cudaGetSymbolAddress((void**)&aol,  g_aol);
    cudaGetSymbolAddress((void**)&wqh,  g_wqh);  cudaGetSymbolAddress((void**)&wql,  g_wql);
    cudaGetSymbolAddress((void**)&wkvh, g_wkvh); cudaGetSymbolAddress((void**)&wkvl, g_wkvl);
    cudaGetSymbolAddress((void**)&woh,  g_woh);  cudaGetSymbolAddress((void**)&wol,  g_wol);
    cudaGetSymbolAddress((void**)&qhh,  g_Qh);   cudaGetSymbolAddress((void**)&qll,  g_Ql);
    cudaGetSymbolAddress((void**)&kvh,  g_KVh);  cudaGetSymbolAddress((void**)&kvl,  g_KVl);
    cudaGetSymbolAddress((void**)&ct,   g_ct);   cudaGetSymbolAddress((void**)&st,   g_st);

    cudaFuncSetAttribute(gemm_pipe<0>, cudaFuncAttributeMaxDynamicSharedMemorySize, GP_SMEM);
    cudaFuncSetAttribute(gemm_pipe<1>, cudaFuncAttributeMaxDynamicSharedMemorySize, GP_SMEM);
    cudaFuncSetAttribute(flash3, cudaFuncAttributeMaxDynamicSharedMemorySize, F3_SMEM);

    // rope tables + conversions
    rope_tab<<<T_SEQ, 64>>>(ct, st);
    conv_hilo8<<<SZ_X / 2048, 256>>>(x, xh, xl, SZ_X);
    conv_t<<<dim3(D_MODEL / 32, D_MODEL / 32), dim3(32, 8)>>>(wq, wqh, wql, D_MODEL, D_MODEL);
    conv_t<<<dim3(KV_DIM / 32, D_MODEL / 32), dim3(32, 8)>>>(wk, wkvh, wkvl, D_MODEL, KV_DIM);
    conv_t<<<dim3(KV_DIM / 32, D_MODEL / 32), dim3(32, 8)>>>(wv, wkvh + (size_t)KV_DIM * D_MODEL,
                                                             wkvl + (size_t)KV_DIM * D_MODEL,
                                                             D_MODEL, KV_DIM);
    conv_t<<<dim3(D_MODEL / 32, D_MODEL / 32), dim3(32, 8)>>>(wo, woh, wol, D_MODEL, D_MODEL);

    // Q projection: fused rope + scale + split (scale includes log2e for exp2 softmax)
    gemm_pipe<1><<<dim3(D_MODEL / 128, T_SEQ / 128), 256, GP_SMEM>>>(
        xh, xl, wqh, wql, nullptr, qhh, qll, ct, st,
        T_SEQ, D_MODEL, D_MODEL, D_MODEL, SCALE * LOG2E, D_MODEL);

    // KV projection: fused rope (K only) + split
    gemm_pipe<1><<<dim3(KV2 / 128, T_SEQ / 128), 256, GP_SMEM>>>(
        xh, xl, wkvh, wkvl, nullptr, kvh, kvl, ct, st,
        T_SEQ, KV2, D_MODEL, KV2, 1.0f, KV_DIM);

    // attention (heavy-first ordering, exp2 softmax, writes bf16 hi/lo)
    flash3<<<dim3(NB, N_HEADS), 256, F3_SMEM>>>(qhh, qll, kvh, kvl, aoh, aol);

    // output projection (fp32 out)
    gemm_pipe<0><<<dim3(D_MODEL / 128, T_SEQ / 128), 256, GP_SMEM>>>(
        aoh, aol, woh, wol, out, nullptr, nullptr, nullptr, nullptr,
        T_SEQ, D_MODEL, D_MODEL, 0, 1.0f, 0);
}

// round 16
// speedup vs baseline: 1.0015x; 1.0015x over previous
#include <cuda_runtime.h>
#include <cuda_bf16.h>
#include <math.h>
#include <stdint.h>

// ---------------------------------------------------------------------------
// LLaMA attention block (sm_103 non-'a' ISA: mma.sync + ldmatrix + cp.async).
// R15 + flash Q-fragments-in-registers + merged weight-conversion kernel.
// GEMMs: bf16x2 split MMA, 2-stage cp.async pipeline, fused epilogues.
// Attention: bf16x2 split FA2, BQ=128, pipelined K/V, heavy-first, exp2.
// ---------------------------------------------------------------------------

#define T_SEQ   2048
#define D_MODEL 4096
#define KV_DIM  1024
#define KV2     2048
#define N_HEADS 32
#define HD      128
#define SCALE   0.08838834764831845f   // 1/sqrt(128)
#define LOG2E   1.4426950408889634f

#define SZ_X    (T_SEQ * D_MODEL)
#define SZ_WQ   (D_MODEL * D_MODEL)
#define SZ_WK   (D_MODEL * KV_DIM)
#define SZ_KV2  (T_SEQ * KV2)

// bf16 hi/lo scratch (weights TRANSPOSED: [N][K]; wkv concatenated on N)
__device__ __nv_bfloat16 g_xh  [SZ_X],   g_xl  [SZ_X];
__device__ __nv_bfloat16 g_aoh [SZ_X],   g_aol [SZ_X];
__device__ __nv_bfloat16 g_wqh [SZ_WQ],  g_wql [SZ_WQ];
__device__ __nv_bfloat16 g_wkvh[2*SZ_WK],g_wkvl[2*SZ_WK];
__device__ __nv_bfloat16 g_woh [SZ_WQ],  g_wol [SZ_WQ];
// attention operands, hi/lo (written by fused GEMM epilogues)
__device__ __nv_bfloat16 g_Qh [SZ_X],   g_Ql [SZ_X];
__device__ __nv_bfloat16 g_KVh[SZ_KV2], g_KVl[SZ_KV2];
// rope tables (fp64-built)
__device__ float g_ct[T_SEQ * 64];
__device__ float g_st[T_SEQ * 64];

// ---------------------------------------------------------------------------
// helpers
// ---------------------------------------------------------------------------
__device__ __forceinline__ uint32_t s2u(const void* p) {
    return (uint32_t)__cvta_generic_to_shared(p);
}
__device__ __forceinline__ void ldmx4(uint32_t& r0, uint32_t& r1,
                                      uint32_t& r2, uint32_t& r3, uint32_t a) {
    asm volatile("ldmatrix.sync.aligned.m8n8.x4.shared.b16 {%0,%1,%2,%3},[%4];\n"
                 : "=r"(r0), "=r"(r1), "=r"(r2), "=r"(r3) : "r"(a));
}
__device__ __forceinline__ void ldmx4t(uint32_t& r0, uint32_t& r1,
                                       uint32_t& r2, uint32_t& r3, uint32_t a) {
    asm volatile("ldmatrix.sync.aligned.m8n8.x4.trans.shared.b16 {%0,%1,%2,%3},[%4];\n"
                 : "=r"(r0), "=r"(r1), "=r"(r2), "=r"(r3) : "r"(a));
}
__device__ __forceinline__ void mma16816(float* d, uint32_t a0, uint32_t a1,
                                         uint32_t a2, uint32_t a3,
                                         uint32_t b0, uint32_t b1) {
    asm volatile(
        "mma.sync.aligned.m16n8k16.row.col.f32.bf16.bf16.f32 "
        "{%0,%1,%2,%3},{%4,%5,%6,%7},{%8,%9},{%0,%1,%2,%3};\n"
        : "+f"(d[0]), "+f"(d[1]), "+f"(d[2]), "+f"(d[3])
        : "r"(a0), "r"(a1), "r"(a2), "r"(a3), "r"(b0), "r"(b1));
}
__device__ __forceinline__ void split_hl(float v, __nv_bfloat16& h, __nv_bfloat16& l) {
    h = __float2bfloat16(v);
    l = __float2bfloat16(v - __bfloat162float(h));
}
__device__ __forceinline__ uint32_t pack_hl(float a, float b, uint32_t& lo) {
    __nv_bfloat16 ha, la, hb, lb;
    split_hl(a, ha, la);
    split_hl(b, hb, lb);
    __nv_bfloat162 H; H.x = ha; H.y = hb;
    __nv_bfloat162 L; L.x = la; L.y = lb;
    lo = *(uint32_t*)&L;
    return *(uint32_t*)&H;
}
__device__ __forceinline__ void cpa16(uint32_t s, const void* g) {
    asm volatile("cp.async.cg.shared.global [%0], [%1], 16;" :: "r"(s), "l"(g));
}

// ---------------------------------------------------------------------------
// rope tables (fp64 trig, computed once)
// ---------------------------------------------------------------------------
__global__ void rope_tab(float* __restrict__ ct, float* __restrict__ st)
{
    const int t = blockIdx.x;
    const int j = threadIdx.x;           // 64 threads
    const double fj = pow(10000.0, -(double)j / 64.0);
    const double a  = (double)t * fj;
    ct[t * 64 + j] = (float)cos(a);
    st[t * 64 + j] = (float)sin(a);
}

// ---------------------------------------------------------------------------
// fp32 -> bf16 hi/lo, 8 elems/thread
// ---------------------------------------------------------------------------
__global__ __launch_bounds__(256)
void conv_hilo8(const float* __restrict__ s, __nv_bfloat16* __restrict__ h,
                __nv_bfloat16* __restrict__ l, int n)
{
    int i = (blockIdx.x * blockDim.x + threadIdx.x) * 8;
    if (i >= n) return;
    float4 v0 = *(const float4*)(s + i);
    float4 v1 = *(const float4*)(s + i + 4);
    __nv_bfloat16 hh[8], ll[8];
    split_hl(v0.x, hh[0], ll[0]); split_hl(v0.y, hh[1], ll[1]);
    split_hl(v0.z, hh[2], ll[2]); split_hl(v0.w, hh[3], ll[3]);
    split_hl(v1.x, hh[4], ll[4]); split_hl(v1.y, hh[5], ll[5]);
    split_hl(v1.z, hh[6], ll[6]); split_hl(v1.w, hh[7], ll[7]);
    *(uint4*)(h + i) = *(uint4*)hh;
    *(uint4*)(l + i) = *(uint4*)ll;
}

// ---------------------------------------------------------------------------
// merged conversion + transpose for all four weights.
// W [4096,N] fp32 -> Wt hi/lo [N,4096] bf16.
// grid.x in [0,320): [0,128)=wq, [128,160)=wk, [160,192)=wv, [192,320)=wo.
// grid.y = k block (128).
// ---------------------------------------------------------------------------
__global__ __launch_bounds__(256)
void conv_t_all(const float* __restrict__ wq, const float* __restrict__ wk,
                const float* __restrict__ wv, const float* __restrict__ wo,
                __nv_bfloat16* __restrict__ wqh, __nv_bfloat16* __restrict__ wql,
                __nv_bfloat16* __restrict__ wkvh, __nv_bfloat16* __restrict__ wkvl,
                __nv_bfloat16* __restrict__ woh, __nv_bfloat16* __restrict__ wol)
{
    __shared__ float tile[32][33];
    const int bx = blockIdx.x;
    const int k0 = blockIdx.y * 32;
    const int tx = threadIdx.x, ty = threadIdx.y;   // 32 x 8

    const float* w;
    __nv_bfloat16 *th, *tl;
    int n0, N;
    if (bx < 128) {
        w = wq;  th = wqh;  tl = wql;  n0 = bx * 32;          N = D_MODEL;
    } else if (bx < 160) {
        w = wk;  th = wkvh; tl = wkvl; n0 = (bx - 128) * 32;  N = KV_DIM;
    } else if (bx < 192) {
        w = wv;  th = wkvh + (size_t)KV_DIM * D_MODEL;
                 tl = wkvl + (size_t)KV_DIM * D_MODEL;
                 n0 = (bx - 160) * 32;  N = KV_DIM;
    } else {
        w = wo;  th = woh;  tl = wol;  n0 = (bx - 192) * 32;  N = D_MODEL;
    }

#pragma unroll
    for (int i = 0; i < 4; i++)
        tile[ty + 8 * i][tx] = w[(size_t)(k0 + ty + 8 * i) * N + n0 + tx];
    __syncthreads();
#pragma unroll
    for (int i = 0; i < 4; i++) {
        float v = tile[tx][ty + 8 * i];
        __nv_bfloat16 h, l;
        split_hl(v, h, l);
        size_t o = (size_t)(n0 + ty + 8 * i) * D_MODEL + k0 + tx;
        th[o] = h;
        tl[o] = l;
    }
}

// ---------------------------------------------------------------------------
// bf16x2-split MMA GEMM, 2-stage cp.async pipeline, templated epilogue.
// MODE 0: C fp32.  MODE 1: rope(+scale)+split -> Dh/Dl bf16 (rope iff
// n0 < rope_limit).
// ---------------------------------------------------------------------------
#define GP_MATE 5120
#define GP_STGE (4 * GP_MATE)
#define GP_SMEM (2 * GP_STGE * 2)

template<int MODE>
__global__ __launch_bounds__(256)
void gemm_pipe(const __nv_bfloat16* __restrict__ Ah, const __nv_bfloat16* __restrict__ Al,
               const __nv_bfloat16* __restrict__ Bh, const __nv_bfloat16* __restrict__ Bl,
               float* __restrict__ C,
               __nv_bfloat16* __restrict__ Dh, __nv_bfloat16* __restrict__ Dl,
               const float* __restrict__ ctab, const float* __restrict__ stab,
               int M, int N, int K, int dstride, float scale, int rope_limit)
{
    extern __shared__ __nv_bfloat16 smg[];
    const uint32_t smbase = s2u(smg);

    const int tid  = threadIdx.x;
    const int lane = tid & 31;
    const int wid  = tid >> 5;
    const int m0 = blockIdx.y * 128, n0 = blockIdx.x * 128;
    const int wm = (wid & 1) * 64;
    const int wn = (wid >> 1) * 32;

    const int r0 = tid >> 2;
    const int o0 = (tid & 3) * 8;
    const int r1 = r0 + 64;

    float acc[4][4][4];
#pragma unroll
    for (int a = 0; a < 4; a++)
#pragma unroll
        for (int b = 0; b < 4; b++)
#pragma unroll
            for (int c = 0; c < 4; c++) acc[a][b][c] = 0.f;

    const int a_row = ((lane >> 3) & 1) * 8 + (lane & 7);
    const int a_col = (lane >> 4) * 8;
    const int b_row = ((lane >> 4) & 1) * 8 + (lane & 7);
    const int b_col = ((lane >> 3) & 1) * 8;

    const int NI = K / 32;

#define GP_ISSUE(st, kk0)                                                       \
    do {                                                                        \
        const uint32_t sb = smbase + (st) * (GP_STGE * 2);                      \
        cpa16(sb + (r0 * 40 + o0) * 2, Ah + (size_t)(m0 + r0) * K + (kk0) + o0);\
        cpa16(sb + (r1 * 40 + o0) * 2, Ah + (size_t)(m0 + r1) * K + (kk0) + o0);\
        cpa16(sb + (GP_MATE + r0 * 40 + o0) * 2,                                \
              Al + (size_t)(m0 + r0) * K + (kk0) + o0);                         \
        cpa16(sb + (GP_MATE + r1 * 40 + o0) * 2,                                \
              Al + (size_t)(m0 + r1) * K + (kk0) + o0);                         \
        cpa16(sb + (2 * GP_MATE + r0 * 40 + o0) * 2,                            \
              Bh + (size_t)(n0 + r0) * K + (kk0) + o0);                         \
        cpa16(sb + (2 * GP_MATE + r1 * 40 + o0) * 2,                            \
              Bh + (size_t)(n0 + r1) * K + (kk0) + o0);                         \
        cpa16(sb + (3 * GP_MATE + r0 * 40 + o0) * 2,                            \
              Bl + (size_t)(n0 + r0) * K + (kk0) + o0);                         \
        cpa16(sb + (3 * GP_MATE + r1 * 40 + o0) * 2,                            \
              Bl + (size_t)(n0 + r1) * K + (kk0) + o0);                         \
        asm volatile("cp.async.commit_group;");                                 \
    } while (0)

    GP_ISSUE(0, 0);

    for (int it = 0; it < NI; it++) {
        const int st = it & 1;
        if (it + 1 < NI) {
            GP_ISSUE(it & 1 ? 0 : 1, (it + 1) * 32);
            asm volatile("cp.async.wait_group 1;");
        } else {
            asm volatile("cp.async.wait_group 0;");
        }
        __syncthreads();

        const __nv_bfloat16* pAh = smg + st * GP_STGE;
        const __nv_bfloat16* pAl = pAh + GP_MATE;
        const __nv_bfloat16* pBh = pAh + 2 * GP_MATE;
        const __nv_bfloat16* pBl = pAh + 3 * GP_MATE;

#pragma unroll
        for (int kk = 0; kk < 32; kk += 16) {
            uint32_t ah[4][4], al[4][4], bh[4][2], bl[4][2];
#pragma unroll
            for (int mi = 0; mi < 4; mi++) {
                ldmx4(ah[mi][0], ah[mi][1], ah[mi][2], ah[mi][3],
                      s2u(pAh + (wm + 16 * mi + a_row) * 40 + kk + a_col));
                ldmx4(al[mi][0], al[mi][1], al[mi][2], al[mi][3],
                      s2u(pAl + (wm + 16 * mi + a_row) * 40 + kk + a_col));
            }
#pragma unroll
            for (int nj = 0; nj < 2; nj++) {
                uint32_t t0, t1, t2, t3;
                ldmx4(t0, t1, t2, t3,
                      s2u(pBh + (wn + 16 * nj + b_row) * 40 + kk + b_col));
                bh[2 * nj][0] = t0; bh[2 * nj][1] = t1;
                bh[2 * nj + 1][0] = t2; bh[2 * nj + 1][1] = t3;
                ldmx4(t0, t1, t2, t3,
                      s2u(pBl + (wn + 16 * nj + b_row) * 40 + kk + b_col));
                bl[2 * nj][0] = t0; bl[2 * nj][1] = t1;
                bl[2 * nj + 1][0] = t2; bl[2 * nj + 1][1] = t3;
            }
#pragma unroll
            for (int mi = 0; mi < 4; mi++)
#pragma unroll
                for (int ni = 0; ni < 4; ni++) {
                    mma16816(acc[mi][ni], ah[mi][0], ah[mi][1], ah[mi][2], ah[mi][3],
                             bh[ni][0], bh[ni][1]);
                    mma16816(acc[mi][ni], ah[mi][0], ah[mi][1], ah[mi][2], ah[mi][3],
                             bl[ni][0], bl[ni][1]);
                    mma16816(acc[mi][ni], al[mi][0], al[mi][1], al[mi][2], al[mi][3],
                             bh[ni][0], bh[ni][1]);
                }
        }
        __syncthreads();
    }
#undef GP_ISSUE

    const int g  = lane >> 2;
    const int t2 = (lane & 3) * 2;

    if (MODE == 0) {
#pragma unroll
        for (int mi = 0; mi < 4; mi++)
#pragma unroll
            for (int ni = 0; ni < 4; ni++) {
                const int row = m0 + wm + 16 * mi + g;
                const int col = n0 + wn + 8 * ni + t2;
                *(float2*)&C[(size_t)row * N + col] =
                    make_float2(acc[mi][ni][0], acc[mi][ni][1]);
                *(float2*)&C[(size_t)(row + 8) * N + col] =
                    make_float2(acc[mi][ni][2], acc[mi][ni][3]);
            }
    } else {
        // stage fp32 tile to smem (stride 132), then rope+scale+split
        float* ft = (float*)smg;
        __syncthreads();
#pragma unroll
        for (int mi = 0; mi < 4; mi++)
#pragma unroll
            for (int ni = 0; ni < 4; ni++) {
                const int rr = wm + 16 * mi + g;
                const int cc = wn + 8 * ni + t2;
                ft[rr * 132 + cc]           = acc[mi][ni][0];
                ft[rr * 132 + cc + 1]       = acc[mi][ni][1];
                ft[(rr + 8) * 132 + cc]     = acc[mi][ni][2];
                ft[(rr + 8) * 132 + cc + 1] = acc[mi][ni][3];
            }
        __syncthreads();

        const int r  = tid >> 1;           // 0..127
        const int jh = (tid & 1) * 32;     // 0 or 32
        const int t  = m0 + r;             // sequence position
        const bool dorope = (n0 < rope_limit);
        const float* crow = ctab + t * 64;
        const float* srow = stab + t * 64;

#pragma unroll
        for (int blk = 0; blk < 4; blk++) {
            __nv_bfloat16 h0[8], l0[8], h1[8], l1[8];
#pragma unroll
            for (int jj = 0; jj < 8; jj++) {
                const int j = jh + blk * 8 + jj;
                float a = ft[r * 132 + j];
                float b = ft[r * 132 + j + 64];
                float na, nb;
                if (dorope) {
                    const float c = crow[j], s = srow[j];
                    na = a * c - b * s;
                    nb = b * c + a * s;
                } else { na = a; nb = b; }
                na *= scale; nb *= scale;
                split_hl(na, h0[jj], l0[jj]);
                split_hl(nb, h1[jj], l1[jj]);
            }
            const size_t base = (size_t)t * dstride + n0 + jh + blk * 8;
            *(uint4*)(Dh + base)      = *(uint4*)h0;
            *(uint4*)(Dl + base)      = *(uint4*)l0;
            *(uint4*)(Dh + base + 64) = *(uint4*)h1;
            *(uint4*)(Dl + base + 64) = *(uint4*)l1;
        }
    }
}

// ---------------------------------------------------------------------------
// Flash attention FA2, bf16x2 split, BQ=128, pipelined K/V, bf16 hi/lo out.
// Heavy-first ordering.  exp2 softmax.  Q fragments held in registers.
// ---------------------------------------------------------------------------
#define FST  136
#define QT   (128 * FST)
#define KVT  (64 * FST)
#define F3_SMEM ((2 * QT + 8 * KVT) * 2)
#define NB   (T_SEQ / 128)

__global__ __launch_bounds__(256)
void flash3(const __nv_bfloat16* __restrict__ Qh, const __nv_bfloat16* __restrict__ Ql,
            const __nv_bfloat16* __restrict__ KVh, const __nv_bfloat16* __restrict__ KVl,
            __nv_bfloat16* __restrict__ AOh, __nv_bfloat16* __restrict__ AOl)
{
    extern __shared__ __nv_bfloat16 smf[];
    __nv_bfloat16* sQh = smf;
    __nv_bfloat16* sQl = sQh + QT;
    __nv_bfloat16* sKV = sQl + QT;
    const uint32_t kvbase = s2u(sKV);

    const int tid  = threadIdx.x;
    const int lane = tid & 31;
    const int wid  = tid >> 5;
    const int wm   = wid * 16;
    const int qb   = NB - 1 - blockIdx.x;   // heavy-first ordering
    const int h    = blockIdx.y;
    const int kh   = h >> 2;

    const int a_row = ((lane >> 3) & 1) * 8 + (lane & 7);
    const int a_col = (lane >> 4) * 8;
    const int b_row = ((lane >> 4) & 1) * 8 + (lane & 7);
    const int b_col = ((lane >> 3) & 1) * 8;
    const int v_row = lane & 15;
    const int v_col = (lane >> 4) * 8;
    const int g     = lane >> 2;
    const int t2    = (lane & 3) * 2;

    const int qr = tid >> 1;
    const int qc = (tid & 1) * 64;
    {
        const __nv_bfloat16* gq0 = Qh + (size_t)(qb * 128 + qr) * D_MODEL + h * HD + qc;
        const __nv_bfloat16* gq1 = Ql + (size_t)(qb * 128 + qr) * D_MODEL + h * HD + qc;
#pragma unroll
        for (int i = 0; i < 8; i++) {
            *(uint4*)&sQh[qr * FST + qc + i * 8] = *(const uint4*)(gq0 + i * 8);
            *(uint4*)&sQl[qr * FST + qc + i * 8] = *(const uint4*)(gq1 + i * 8);
        }
    }
    __syncthreads();   // Q tile visible to all warps for fragment loads

    const int kr = tid >> 2;
    const int kc = (tid & 3) * 32;
    const int ntiles = 2 * qb + 2;

#define F3_ISSUE(jtv)                                                            \
    do {                                                                         \
        const int _st = (jtv) & 1;                                               \
        const int _j0 = (jtv) * 64;                                              \
        const uint32_t sb = kvbase + _st * (4 * KVT) * 2;                        \
        const __nv_bfloat16* khg = KVh + (size_t)(_j0 + kr) * KV2 + kh * HD + kc;\
        const __nv_bfloat16* klg = KVl + (size_t)(_j0 + kr) * KV2 + kh * HD + kc;\
        const __nv_bfloat16* vhg = khg + KV_DIM;                                 \
        const __nv_bfloat16* vlg = klg + KV_DIM;                                 \
        _Pragma("unroll")                                                        \
        for (int i = 0; i < 4; i++) {                                            \
            const uint32_t so = (kr * FST + kc + i * 8) * 2;                     \
            cpa16(sb + so,               khg + i * 8);                           \
            cpa16(sb + KVT * 2 + so,     klg + i * 8);                           \
            cpa16(sb + 2 * KVT * 2 + so, vhg + i * 8);                           \
            cpa16(sb + 3 * KVT * 2 + so, vlg + i * 8);                           \
        }                                                                        \
        asm volatile("cp.async.commit_group;");                                  \
    } while (0)

    F3_ISSUE(0);

    // Q fragments -> registers (overlaps with first KV cp.async)
    uint32_t qfh[8][4], qfl[8][4];
#pragma unroll
    for (int kk = 0; kk < 8; kk++) {
        ldmx4(qfh[kk][0], qfh[kk][1], qfh[kk][2], qfh[kk][3],
              s2u(&sQh[(wm + a_row) * FST + kk * 16 + a_col]));
        ldmx4(qfl[kk][0], qfl[kk][1], qfl[kk][2], qfl[kk][3],
              s2u(&sQl[(wm + a_row) * FST + kk * 16 + a_col]));
    }

    float o[16][4];
#pragma unroll
    for (int i = 0; i < 16; i++)
#pragma unroll
        for (int j = 0; j < 4; j++) o[i][j] = 0.f;
    float m0r = -1e30f, m1r = -1e30f, l0r = 0.f, l1r = 0.f;

    for (int jt = 0; jt < ntiles; jt++) {
        const int st = jt & 1;
        const int j0 = jt * 64;
        if (jt + 1 < ntiles) {
            F3_ISSUE(jt + 1);
            asm volatile("cp.async.wait_group 1;");
        } else {
            asm volatile("cp.async.wait_group 0;");
        }
        __syncthreads();

        const __nv_bfloat16* sKh = sKV + st * 4 * KVT;
        const __nv_bfloat16* sKl = sKh + KVT;
        const __nv_bfloat16* sVh = sKh + 2 * KVT;
        const __nv_bfloat16* sVl = sKh + 3 * KVT;

        float sa[8][4];
#pragma unroll
        for (int c = 0; c < 8; c++)
#pragma unroll
            for (int j = 0; j < 4; j++) sa[c][j] = 0.f;

#pragma unroll
        for (int kk = 0; kk < 8; kk++) {
#pragma unroll
            for (int njp = 0; njp < 4; njp++) {
                uint32_t bh0, bh1, bh2, bh3, bl0, bl1, bl2, bl3;
                ldmx4(bh0, bh1, bh2, bh3,
                      s2u(sKh + (njp * 16 + b_row) * FST + kk * 16 + b_col));
                ldmx4(bl0, bl1, bl2, bl3,
                      s2u(sKl + (njp * 16 + b_row) * FST + kk * 16 + b_col));
                mma16816(sa[2 * njp], qfh[kk][0], qfh[kk][1], qfh[kk][2], qfh[kk][3], bh0, bh1);
                mma16816(sa[2 * njp], qfh[kk][0], qfh[kk][1], qfh[kk][2], qfh[kk][3], bl0, bl1);
                mma16816(sa[2 * njp], qfl[kk][0], qfl[kk][1], qfl[kk][2], qfl[kk][3], bh0, bh1);
                mma16816(sa[2 * njp + 1], qfh[kk][0], qfh[kk][1], qfh[kk][2], qfh[kk][3], bh2, bh3);
                mma16816(sa[2 * njp + 1], qfh[kk][0], qfh[kk][1], qfh[kk][2], qfh[kk][3], bl2, bl3);
                mma16816(sa[2 * njp + 1], qfl[kk][0], qfl[kk][1], qfl[kk][2], qfl[kk][3], bh2, bh3);
            }
        }

        if (jt >= ntiles - 2) {
            const int qr0 = qb * 128 + wm + g;
            const int qr1 = qr0 + 8;
#pragma unroll
            for (int c = 0; c < 8; c++) {
                const int col = j0 + c * 8 + t2;
                if (col     > qr0) sa[c][0] = -1e30f;
                if (col + 1 > qr0) sa[c][1] = -1e30f;
                if (col     > qr1) sa[c][2] = -1e30f;
                if (col + 1 > qr1) sa[c][3] = -1e30f;
            }
        }

        float rm0 = -1e30f, rm1 = -1e30f;
#pragma unroll
        for (int c = 0; c < 8; c++) {
            rm0 = fmaxf(rm0, fmaxf(sa[c][0], sa[c][1]));
            rm1 = fmaxf(rm1, fmaxf(sa[c][2], sa[c][3]));
        }
        rm0 = fmaxf(rm0, __shfl_xor_sync(0xffffffffu, rm0, 1));
        rm0 = fmaxf(rm0, __shfl_xor_sync(0xffffffffu, rm0, 2));
        rm1 = fmaxf(rm1, __shfl_xor_sync(0xffffffffu, rm1, 1));
        rm1 = fmaxf(rm1, __shfl_xor_sync(0xffffffffu, rm1, 2));

        const float mn0 = fmaxf(m0r, rm0);
        const float mn1 = fmaxf(m1r, rm1);

        if (mn0 != m0r || mn1 != m1r) {
            const float al0 = exp2f(m0r - mn0);
            const float al1 = exp2f(m1r - mn1);
            l0r *= al0;
            l1r *= al1;
#pragma unroll
            for (int dj = 0; dj < 16; dj++) {
                o[dj][0] *= al0;
                o[dj][1] *= al0;
                o[dj][2] *= al1;
                o[dj][3] *= al1;
            }
            m0r = mn0;
            m1r = mn1;
        }

        float rs0 = 0.f, rs1 = 0.f;
#pragma unroll
        for (int c = 0; c < 8; c++) {
            sa[c][0] = exp2f(sa[c][0] - m0r);
            sa[c][1] = exp2f(sa[c][1] - m0r);
            sa[c][2] = exp2f(sa[c][2] - m1r);
            sa[c][3] = exp2f(sa[c][3] - m1r);
            rs0 += sa[c][0] + sa[c][1];
            rs1 += sa[c][2] + sa[c][3];
        }
        rs0 += __shfl_xor_sync(0xffffffffu, rs0, 1);
        rs0 += __shfl_xor_sync(0xffffffffu, rs0, 2);
        rs1 += __shfl_xor_sync(0xffffffffu, rs1, 1);
        rs1 += __shfl_xor_sync(0xffffffffu, rs1, 2);

        l0r += rs0;
        l1r += rs1;

#pragma unroll
        for (int ks = 0; ks < 4; ks++) {
            const int c0 = 2 * ks, c1 = 2 * ks + 1;
            uint32_t pl0, pl1, pl2, pl3;
            const uint32_t ph0 = pack_hl(sa[c0][0], sa[c0][1], pl0);
            const uint32_t ph1 = pack_hl(sa[c0][2], sa[c0][3], pl1);
            const uint32_t ph2 = pack_hl(sa[c1][0], sa[c1][1], pl2);
            const uint32_t ph3 = pack_hl(sa[c1][2], sa[c1][3], pl3);
#pragma unroll
            for (int djp = 0; djp < 8; djp++) {
                uint32_t vh0, vh1, vh2, vh3, vl0, vl1, vl2, vl3;
                ldmx4t(vh0, vh1, vh2, vh3,
                       s2u(sVh + (ks * 16 + v_row) * FST + djp * 16 + v_col));
                ldmx4t(vl0, vl1, vl2, vl3,
                       s2u(sVl + (ks * 16 + v_row) * FST + djp * 16 + v_col));
                mma16816(o[2 * djp], ph0, ph1, ph2, ph3, vh0, vh1);
                mma16816(o[2 * djp], ph0, ph1, ph2, ph3, vl0, vl1);
                mma16816(o[2 * djp], pl0, pl1, pl2, pl3, vh0, vh1);
                mma16816(o[2 * djp + 1], ph0, ph1, ph2, ph3, vh2, vh3);
                mma16816(o[2 * djp + 1], ph0, ph1, ph2, ph3, vl2, vl3);
                mma16816(o[2 * djp + 1], pl0, pl1, pl2, pl3, vh2, vh3);
            }
        }
        __syncthreads();
    }
#undef F3_ISSUE

    // epilogue: normalize + hi/lo split directly to bf16
    const float inv0 = 1.0f / l0r;
    const float inv1 = 1.0f / l1r;
    const int row0 = qb * 128 + wm + g;
    const int row1 = row0 + 8;
#pragma unroll
    for (int dj = 0; dj < 16; dj++) {
        uint32_t lo;
        uint32_t hi = pack_hl(o[dj][0] * inv0, o[dj][1] * inv0, lo);
        const size_t b0 = (size_t)row0 * D_MODEL + h * HD + dj * 8 + t2;
        *(uint32_t*)(AOh + b0) = hi;
        *(uint32_t*)(AOl + b0) = lo;
        hi = pack_hl(o[dj][2] * inv1, o[dj][3] * inv1, lo);
        const size_t b1 = (size_t)row1 * D_MODEL + h * HD + dj * 8 + t2;
        *(uint32_t*)(AOh + b1) = hi;
        *(uint32_t*)(AOl + b1) = lo;
    }
}

// ---------------------------------------------------------------------------
// launch — signature order: x, wq, wk, wv, wo
// ---------------------------------------------------------------------------
extern "C" void kernel_launch(void* const* d_in, const int* in_sizes, int n_in,
                              void* d_out, int out_size)
{
    const float* x  = (const float*)d_in[0];
    const float* wq = (const float*)d_in[1];
    const float* wk = (const float*)d_in[2];
    const float* wv = (const float*)d_in[3];
    const float* wo = (const float*)d_in[4];
    float* out = (float*)d_out;

    __nv_bfloat16 *xh, *xl, *aoh, *aol, *wqh, *wql, *wkvh, *wkvl, *woh, *wol;
    __nv_bfloat16 *qhh, *qll, *kvh, *kvl;
    float *ct, *st;
    cudaGetSymbolAddress((void**)&xh,   g_xh);   cudaGetSymbolAddress((void**)&xl,   g_xl);
    cudaGetSymbolAddress((void**)&aoh,  g_aoh);  cudaGetSymbolAddress((void**)&aol,  g_aol);
    cudaGetSymbolAddress((void**)&wqh,  g_wqh);  cudaGetSymbolAddress((void**)&wql,  g_wql);
    cudaGetSymbolAddress((void**)&wkvh, g_wkvh); cudaGetSymbolAddress((void**)&wkvl, g_wkvl);
    cudaGetSymbolAddress((void**)&woh,  g_woh);  cudaGetSymbolAddress((void**)&wol,  g_wol);
    cudaGetSymbolAddress((void**)&qhh,  g_Qh);   cudaGetSymbolAddress((void**)&qll,  g_Ql);
    cudaGetSymbolAddress((void**)&kvh,  g_KVh);  cudaGetSymbolAddress((void**)&kvl,  g_KVl);
    cudaGetSymbolAddress((void**)&ct,   g_ct);   cudaGetSymbolAddress((void**)&st,   g_st);

    cudaFuncSetAttribute(gemm_pipe<0>, cudaFuncAttributeMaxDynamicSharedMemorySize, GP_SMEM);
    cudaFuncSetAttribute(gemm_pipe<1>, cudaFuncAttributeMaxDynamicSharedMemorySize, GP_SMEM);
    cudaFuncSetAttribute(flash3, cudaFuncAttributeMaxDynamicSharedMemorySize, F3_SMEM);

    // rope tables + conversions (weights merged into one launch)
    rope_tab<<<T_SEQ, 64>>>(ct, st);
    conv_hilo8<<<SZ_X / 2048, 256>>>(x, xh, xl, SZ_X);
    conv_t_all<<<dim3(320, 128), dim3(32, 8)>>>(wq, wk, wv, wo,
                                                wqh, wql, wkvh, wkvl, woh, wol);

    // Q projection: fused rope + scale + split (scale includes log2e)
    gemm_pipe<1><<<dim3(D_MODEL / 128, T_SEQ / 128), 256, GP_SMEM>>>(
        xh, xl, wqh, wql, nullptr, qhh, qll, ct, st,
        T_SEQ, D_MODEL, D_MODEL, D_MODEL, SCALE * LOG2E, D_MODEL);

    // KV projection: fused rope (K only) + split
    gemm_pipe<1><<<dim3(KV2 / 128, T_SEQ / 128), 256, GP_SMEM>>>(
        xh, xl, wkvh, wkvl, nullptr, kvh, kvl, ct, st,
        T_SEQ, KV2, D_MODEL, KV2, 1.0f, KV_DIM);

    // attention (heavy-first, exp2 softmax, Q-in-registers)
    flash3<<<dim3(NB, N_HEADS), 256, F3_SMEM>>>(qhh, qll, kvh, kvl, aoh, aol);

    // output projection (fp32 out)
    gemm_pipe<0><<<dim3(D_MODEL / 128, T_SEQ / 128), 256, GP_SMEM>>>(
        aoh, aol, woh, wol, out, nullptr, nullptr, nullptr, nullptr,
        T_SEQ, D_MODEL, D_MODEL, 0, 1.0f, 0);
}

// round 17
// speedup vs baseline: 1.0022x; 1.0007x over previous
#include <cuda_runtime.h>
#include <cuda_bf16.h>
#include <math.h>
#include <stdint.h>

// ---------------------------------------------------------------------------
// LLaMA attention block (sm_103 non-'a' ISA: mma.sync + ldmatrix + cp.async).
// R16 + GEMM MMA pass-reordering (hh/hl/lh emitted as separate full passes
// to break accumulator RAW chains; per-acc order preserved -> bitwise equal).
// ---------------------------------------------------------------------------

#define T_SEQ   2048
#define D_MODEL 4096
#define KV_DIM  1024
#define KV2     2048
#define N_HEADS 32
#define HD      128
#define SCALE   0.08838834764831845f   // 1/sqrt(128)
#define LOG2E   1.4426950408889634f

#define SZ_X    (T_SEQ * D_MODEL)
#define SZ_WQ   (D_MODEL * D_MODEL)
#define SZ_WK   (D_MODEL * KV_DIM)
#define SZ_KV2  (T_SEQ * KV2)

// bf16 hi/lo scratch (weights TRANSPOSED: [N][K]; wkv concatenated on N)
__device__ __nv_bfloat16 g_xh  [SZ_X],   g_xl  [SZ_X];
__device__ __nv_bfloat16 g_aoh [SZ_X],   g_aol [SZ_X];
__device__ __nv_bfloat16 g_wqh [SZ_WQ],  g_wql [SZ_WQ];
__device__ __nv_bfloat16 g_wkvh[2*SZ_WK],g_wkvl[2*SZ_WK];
__device__ __nv_bfloat16 g_woh [SZ_WQ],  g_wol [SZ_WQ];
// attention operands, hi/lo (written by fused GEMM epilogues)
__device__ __nv_bfloat16 g_Qh [SZ_X],   g_Ql [SZ_X];
__device__ __nv_bfloat16 g_KVh[SZ_KV2], g_KVl[SZ_KV2];
// rope tables (fp64-built)
__device__ float g_ct[T_SEQ * 64];
__device__ float g_st[T_SEQ * 64];

// ---------------------------------------------------------------------------
// helpers
// ---------------------------------------------------------------------------
__device__ __forceinline__ uint32_t s2u(const void* p) {
    return (uint32_t)__cvta_generic_to_shared(p);
}
__device__ __forceinline__ void ldmx4(uint32_t& r0, uint32_t& r1,
                                      uint32_t& r2, uint32_t& r3, uint32_t a) {
    asm volatile("ldmatrix.sync.aligned.m8n8.x4.shared.b16 {%0,%1,%2,%3},[%4];\n"
                 : "=r"(r0), "=r"(r1), "=r"(r2), "=r"(r3) : "r"(a));
}
__device__ __forceinline__ void ldmx4t(uint32_t& r0, uint32_t& r1,
                                       uint32_t& r2, uint32_t& r3, uint32_t a) {
    asm volatile("ldmatrix.sync.aligned.m8n8.x4.trans.shared.b16 {%0,%1,%2,%3},[%4];\n"
                 : "=r"(r0), "=r"(r1), "=r"(r2), "=r"(r3) : "r"(a));
}
__device__ __forceinline__ void mma16816(float* d, uint32_t a0, uint32_t a1,
                                         uint32_t a2, uint32_t a3,
                                         uint32_t b0, uint32_t b1) {
    asm volatile(
        "mma.sync.aligned.m16n8k16.row.col.f32.bf16.bf16.f32 "
        "{%0,%1,%2,%3},{%4,%5,%6,%7},{%8,%9},{%0,%1,%2,%3};\n"
        : "+f"(d[0]), "+f"(d[1]), "+f"(d[2]), "+f"(d[3])
        : "r"(a0), "r"(a1), "r"(a2), "r"(a3), "r"(b0), "r"(b1));
}
__device__ __forceinline__ void split_hl(float v, __nv_bfloat16& h, __nv_bfloat16& l) {
    h = __float2bfloat16(v);
    l = __float2bfloat16(v - __bfloat162float(h));
}
__device__ __forceinline__ uint32_t pack_hl(float a, float b, uint32_t& lo) {
    __nv_bfloat16 ha, la, hb, lb;
    split_hl(a, ha, la);
    split_hl(b, hb, lb);
    __nv_bfloat162 H; H.x = ha; H.y = hb;
    __nv_bfloat162 L; L.x = la; L.y = lb;
    lo = *(uint32_t*)&L;
    return *(uint32_t*)&H;
}
__device__ __forceinline__ void cpa16(uint32_t s, const void* g) {
    asm volatile("cp.async.cg.shared.global [%0], [%1], 16;" :: "r"(s), "l"(g));
}

// ---------------------------------------------------------------------------
// rope tables (fp64 trig, computed once)
// ---------------------------------------------------------------------------
__global__ void rope_tab(float* __restrict__ ct, float* __restrict__ st)
{
    const int t = blockIdx.x;
    const int j = threadIdx.x;           // 64 threads
    const double fj = pow(10000.0, -(double)j / 64.0);
    const double a  = (double)t * fj;
    ct[t * 64 + j] = (float)cos(a);
    st[t * 64 + j] = (float)sin(a);
}

// ---------------------------------------------------------------------------
// fp32 -> bf16 hi/lo, 8 elems/thread
// ---------------------------------------------------------------------------
__global__ __launch_bounds__(256)
void conv_hilo8(const float* __restrict__ s, __nv_bfloat16* __restrict__ h,
                __nv_bfloat16* __restrict__ l, int n)
{
    int i = (blockIdx.x * blockDim.x + threadIdx.x) * 8;
    if (i >= n) return;
    float4 v0 = *(const float4*)(s + i);
    float4 v1 = *(const float4*)(s + i + 4);
    __nv_bfloat16 hh[8], ll[8];
    split_hl(v0.x, hh[0], ll[0]); split_hl(v0.y, hh[1], ll[1]);
    split_hl(v0.z, hh[2], ll[2]); split_hl(v0.w, hh[3], ll[3]);
    split_hl(v1.x, hh[4], ll[4]); split_hl(v1.y, hh[5], ll[5]);
    split_hl(v1.z, hh[6], ll[6]); split_hl(v1.w, hh[7], ll[7]);
    *(uint4*)(h + i) = *(uint4*)hh;
    *(uint4*)(l + i) = *(uint4*)ll;
}

// ---------------------------------------------------------------------------
// merged conversion + transpose for all four weights.
// ---------------------------------------------------------------------------
__global__ __launch_bounds__(256)
void conv_t_all(const float* __restrict__ wq, const float* __restrict__ wk,
                const float* __restrict__ wv, const float* __restrict__ wo,
                __nv_bfloat16* __restrict__ wqh, __nv_bfloat16* __restrict__ wql,
                __nv_bfloat16* __restrict__ wkvh, __nv_bfloat16* __restrict__ wkvl,
                __nv_bfloat16* __restrict__ woh, __nv_bfloat16* __restrict__ wol)
{
    __shared__ float tile[32][33];
    const int bx = blockIdx.x;
    const int k0 = blockIdx.y * 32;
    const int tx = threadIdx.x, ty = threadIdx.y;   // 32 x 8

    const float* w;
    __nv_bfloat16 *th, *tl;
    int n0, N;
    if (bx < 128) {
        w = wq;  th = wqh;  tl = wql;  n0 = bx * 32;          N = D_MODEL;
    } else if (bx < 160) {
        w = wk;  th = wkvh; tl = wkvl; n0 = (bx - 128) * 32;  N = KV_DIM;
    } else if (bx < 192) {
        w = wv;  th = wkvh + (size_t)KV_DIM * D_MODEL;
                 tl = wkvl + (size_t)KV_DIM * D_MODEL;
                 n0 = (bx - 160) * 32;  N = KV_DIM;
    } else {
        w = wo;  th = woh;  tl = wol;  n0 = (bx - 192) * 32;  N = D_MODEL;
    }

#pragma unroll
    for (int i = 0; i < 4; i++)
        tile[ty + 8 * i][tx] = w[(size_t)(k0 + ty + 8 * i) * N + n0 + tx];
    __syncthreads();
#pragma unroll
    for (int i = 0; i < 4; i++) {
        float v = tile[tx][ty + 8 * i];
        __nv_bfloat16 h, l;
        split_hl(v, h, l);
        size_t o = (size_t)(n0 + ty + 8 * i) * D_MODEL + k0 + tx;
        th[o] = h;
        tl[o] = l;
    }
}

// ---------------------------------------------------------------------------
// bf16x2-split MMA GEMM, 2-stage cp.async pipeline, templated epilogue.
// MMA emission in three full passes (hh/hl/lh) per k-chunk to break acc RAW
// chains; per-accumulator order preserved (bitwise-identical results).
// ---------------------------------------------------------------------------
#define GP_MATE 5120
#define GP_STGE (4 * GP_MATE)
#define GP_SMEM (2 * GP_STGE * 2)

template<int MODE>
__global__ __launch_bounds__(256)
void gemm_pipe(const __nv_bfloat16* __restrict__ Ah, const __nv_bfloat16* __restrict__ Al,
               const __nv_bfloat16* __restrict__ Bh, const __nv_bfloat16* __restrict__ Bl,
               float* __restrict__ C,
               __nv_bfloat16* __restrict__ Dh, __nv_bfloat16* __restrict__ Dl,
               const float* __restrict__ ctab, const float* __restrict__ stab,
               int M, int N, int K, int dstride, float scale, int rope_limit)
{
    extern __shared__ __nv_bfloat16 smg[];
    const uint32_t smbase = s2u(smg);

    const int tid  = threadIdx.x;
    const int lane = tid & 31;
    const int wid  = tid >> 5;
    const int m0 = blockIdx.y * 128, n0 = blockIdx.x * 128;
    const int wm = (wid & 1) * 64;
    const int wn = (wid >> 1) * 32;

    const int r0 = tid >> 2;
    const int o0 = (tid & 3) * 8;
    const int r1 = r0 + 64;

    float acc[4][4][4];
#pragma unroll
    for (int a = 0; a < 4; a++)
#pragma unroll
        for (int b = 0; b < 4; b++)
#pragma unroll
            for (int c = 0; c < 4; c++) acc[a][b][c] = 0.f;

    const int a_row = ((lane >> 3) & 1) * 8 + (lane & 7);
    const int a_col = (lane >> 4) * 8;
    const int b_row = ((lane >> 4) & 1) * 8 + (lane & 7);
    const int b_col = ((lane >> 3) & 1) * 8;

    const int NI = K / 32;

#define GP_ISSUE(st, kk0)                                                       \
    do {                                                                        \
        const uint32_t sb = smbase + (st) * (GP_STGE * 2);                      \
        cpa16(sb + (r0 * 40 + o0) * 2, Ah + (size_t)(m0 + r0) * K + (kk0) + o0);\
        cpa16(sb + (r1 * 40 + o0) * 2, Ah + (size_t)(m0 + r1) * K + (kk0) + o0);\
        cpa16(sb + (GP_MATE + r0 * 40 + o0) * 2,                                \
              Al + (size_t)(m0 + r0) * K + (kk0) + o0);                         \
        cpa16(sb + (GP_MATE + r1 * 40 + o0) * 2,                                \
              Al + (size_t)(m0 + r1) * K + (kk0) + o0);                         \
        cpa16(sb + (2 * GP_MATE + r0 * 40 + o0) * 2,                            \
              Bh + (size_t)(n0 + r0) * K + (kk0) + o0);                         \
        cpa16(sb + (2 * GP_MATE + r1 * 40 + o0) * 2,                            \
              Bh + (size_t)(n0 + r1) * K + (kk0) + o0);                         \
        cpa16(sb + (3 * GP_MATE + r0 * 40 + o0) * 2,                            \
              Bl + (size_t)(n0 + r0) * K + (kk0) + o0);                         \
        cpa16(sb + (3 * GP_MATE + r1 * 40 + o0) * 2,                            \
              Bl + (size_t)(n0 + r1) * K + (kk0) + o0);                         \
        asm volatile("cp.async.commit_group;");                                 \
    } while (0)

    GP_ISSUE(0, 0);

    for (int it = 0; it < NI; it++) {
        const int st = it & 1;
        if (it + 1 < NI) {
            GP_ISSUE(it & 1 ? 0 : 1, (it + 1) * 32);
            asm volatile("cp.async.wait_group 1;");
        } else {
            asm volatile("cp.async.wait_group 0;");
        }
        __syncthreads();

        const __nv_bfloat16* pAh = smg + st * GP_STGE;
        const __nv_bfloat16* pAl = pAh + GP_MATE;
        const __nv_bfloat16* pBh = pAh + 2 * GP_MATE;
        const __nv_bfloat16* pBl = pAh + 3 * GP_MATE;

#pragma unroll
        for (int kk = 0; kk < 32; kk += 16) {
            uint32_t ah[4][4], al[4][4], bh[4][2], bl[4][2];
#pragma unroll
            for (int mi = 0; mi < 4; mi++) {
                ldmx4(ah[mi][0], ah[mi][1], ah[mi][2], ah[mi][3],
                      s2u(pAh + (wm + 16 * mi + a_row) * 40 + kk + a_col));
                ldmx4(al[mi][0], al[mi][1], al[mi][2], al[mi][3],
                      s2u(pAl + (wm + 16 * mi + a_row) * 40 + kk + a_col));
            }
#pragma unroll
            for (int nj = 0; nj < 2; nj++) {
                uint32_t t0, t1, t2, t3;
                ldmx4(t0, t1, t2, t3,
                      s2u(pBh + (wn + 16 * nj + b_row) * 40 + kk + b_col));
                bh[2 * nj][0] = t0; bh[2 * nj][1] = t1;
                bh[2 * nj + 1][0] = t2; bh[2 * nj + 1][1] = t3;
                ldmx4(t0, t1, t2, t3,
                      s2u(pBl + (wn + 16 * nj + b_row) * 40 + kk + b_col));
                bl[2 * nj][0] = t0; bl[2 * nj][1] = t1;
                bl[2 * nj + 1][0] = t2; bl[2 * nj + 1][1] = t3;
            }
            // pass 1: Ah*Bh for all accumulators (16 independent MMAs)
#pragma unroll
            for (int mi = 0; mi < 4; mi++)
#pragma unroll
                for (int ni = 0; ni < 4; ni++)
                    mma16816(acc[mi][ni], ah[mi][0], ah[mi][1], ah[mi][2], ah[mi][3],
                             bh[ni][0], bh[ni][1]);
            // pass 2: Ah*Bl
#pragma unroll
            for (int mi = 0; mi < 4; mi++)
#pragma unroll
                for (int ni = 0; ni < 4; ni++)
                    mma16816(acc[mi][ni], ah[mi][0], ah[mi][1], ah[mi][2], ah[mi][3],
                             bl[ni][0], bl[ni][1]);
            // pass 3: Al*Bh
#pragma unroll
            for (int mi = 0; mi < 4; mi++)
#pragma unroll
                for (int ni = 0; ni < 4; ni++)
                    mma16816(acc[mi][ni], al[mi][0], al[mi][1], al[mi][2], al[mi][3],
                             bh[ni][0], bh[ni][1]);
        }
        __syncthreads();
    }
#undef GP_ISSUE

    const int g  = lane >> 2;
    const int t2 = (lane & 3) * 2;

    if (MODE == 0) {
#pragma unroll
        for (int mi = 0; mi < 4; mi++)
#pragma unroll
            for (int ni = 0; ni < 4; ni++) {
                const int row = m0 + wm + 16 * mi + g;
                const int col = n0 + wn + 8 * ni + t2;
                *(float2*)&C[(size_t)row * N + col] =
                    make_float2(acc[mi][ni][0], acc[mi][ni][1]);
                *(float2*)&C[(size_t)(row + 8) * N + col] =
                    make_float2(acc[mi][ni][2], acc[mi][ni][3]);
            }
    } else {
        // stage fp32 tile to smem (stride 132), then rope+scale+split
        float* ft = (float*)smg;
        __syncthreads();
#pragma unroll
        for (int mi = 0; mi < 4; mi++)
#pragma unroll
            for (int ni = 0; ni < 4; ni++) {
                const int rr = wm + 16 * mi + g;
                const int cc = wn + 8 * ni + t2;
                ft[rr * 132 + cc]           = acc[mi][ni][0];
                ft[rr * 132 + cc + 1]       = acc[mi][ni][1];
                ft[(rr + 8) * 132 + cc]     = acc[mi][ni][2];
                ft[(rr + 8) * 132 + cc + 1] = acc[mi][ni][3];
            }
        __syncthreads();

        const int r  = tid >> 1;           // 0..127
        const int jh = (tid & 1) * 32;     // 0 or 32
        const int t  = m0 + r;             // sequence position
        const bool dorope = (n0 < rope_limit);
        const float* crow = ctab + t * 64;
        const float* srow = stab + t * 64;

#pragma unroll
        for (int blk = 0; blk < 4; blk++) {
            __nv_bfloat16 h0[8], l0[8], h1[8], l1[8];
#pragma unroll
            for (int jj = 0; jj < 8; jj++) {
                const int j = jh + blk * 8 + jj;
                float a = ft[r * 132 + j];
                float b = ft[r * 132 + j + 64];
                float na, nb;
                if (dorope) {
                    const float c = crow[j], s = srow[j];
                    na = a * c - b * s;
                    nb = b * c + a * s;
                } else { na = a; nb = b; }
                na *= scale; nb *= scale;
                split_hl(na, h0[jj], l0[jj]);
                split_hl(nb, h1[jj], l1[jj]);
            }
            const size_t base = (size_t)t * dstride + n0 + jh + blk * 8;
            *(uint4*)(Dh + base)      = *(uint4*)h0;
            *(uint4*)(Dl + base)      = *(uint4*)l0;
            *(uint4*)(Dh + base + 64) = *(uint4*)h1;
            *(uint4*)(Dl + base + 64) = *(uint4*)l1;
        }
    }
}

// ---------------------------------------------------------------------------
// Flash attention FA2, bf16x2 split, BQ=128, pipelined K/V, bf16 hi/lo out.
// Heavy-first ordering.  exp2 softmax.  Q fragments held in registers.
// ---------------------------------------------------------------------------
#define FST  136
#define QT   (128 * FST)
#define KVT  (64 * FST)
#define F3_SMEM ((2 * QT + 8 * KVT) * 2)
#define NB   (T_SEQ / 128)

__global__ __launch_bounds__(256)
void flash3(const __nv_bfloat16* __restrict__ Qh, const __nv_bfloat16* __restrict__ Ql,
            const __nv_bfloat16* __restrict__ KVh, const __nv_bfloat16* __restrict__ KVl,
            __nv_bfloat16* __restrict__ AOh, __nv_bfloat16* __restrict__ AOl)
{
    extern __shared__ __nv_bfloat16 smf[];
    __nv_bfloat16* sQh = smf;
    __nv_bfloat16* sQl = sQh + QT;
    __nv_bfloat16* sKV = sQl + QT;
    const uint32_t kvbase = s2u(sKV);

    const int tid  = threadIdx.x;
    const int lane = tid & 31;
    const int wid  = tid >> 5;
    const int wm   = wid * 16;
    const int qb   = NB - 1 - blockIdx.x;   // heavy-first ordering
    const int h    = blockIdx.y;
    const int kh   = h >> 2;

    const int a_row = ((lane >> 3) & 1) * 8 + (lane & 7);
    const int a_col = (lane >> 4) * 8;
    const int b_row = ((lane >> 4) & 1) * 8 + (lane & 7);
    const int b_col = ((lane >> 3) & 1) * 8;
    const int v_row = lane & 15;
    const int v_col = (lane >> 4) * 8;
    const int g     = lane >> 2;
    const int t2    = (lane & 3) * 2;

    const int qr = tid >> 1;
    const int qc = (tid & 1) * 64;
    {
        const __nv_bfloat16* gq0 = Qh + (size_t)(qb * 128 + qr) * D_MODEL + h * HD + qc;
        const __nv_bfloat16* gq1 = Ql + (size_t)(qb * 128 + qr) * D_MODEL + h * HD + qc;
#pragma unroll
        for (int i = 0; i < 8; i++) {
            *(uint4*)&sQh[qr * FST + qc + i * 8] = *(const uint4*)(gq0 + i * 8);
            *(uint4*)&sQl[qr * FST + qc + i * 8] = *(const uint4*)(gq1 + i * 8);
        }
    }
    __syncthreads();

    const int kr = tid >> 2;
    const int kc = (tid & 3) * 32;
    const int ntiles = 2 * qb + 2;

#define F3_ISSUE(jtv)                                                            \
    do {                                                                         \
        const int _st = (jtv) & 1;                                               \
        const int _j0 = (jtv) * 64;                                              \
        const uint32_t sb = kvbase + _st * (4 * KVT) * 2;                        \
        const __nv_bfloat16* khg = KVh + (size_t)(_j0 + kr) * KV2 + kh * HD + kc;\
        const __nv_bfloat16* klg = KVl + (size_t)(_j0 + kr) * KV2 + kh * HD + kc;\
        const __nv_bfloat16* vhg = khg + KV_DIM;                                 \
        const __nv_bfloat16* vlg = klg + KV_DIM;                                 \
        _Pragma("unroll")                                                        \
        for (int i = 0; i < 4; i++) {                                            \
            const uint32_t so = (kr * FST + kc + i * 8) * 2;                     \
            cpa16(sb + so,               khg + i * 8);                           \
            cpa16(sb + KVT * 2 + so,     klg + i * 8);                           \
            cpa16(sb + 2 * KVT * 2 + so, vhg + i * 8);                           \
            cpa16(sb + 3 * KVT * 2 + so, vlg + i * 8);                           \
        }                                                                        \
        asm volatile("cp.async.commit_group;");                                  \
    } while (0)

    F3_ISSUE(0);

    // Q fragments -> registers (overlaps with first KV cp.async)
    uint32_t qfh[8][4], qfl[8][4];
#pragma unroll
    for (int kk = 0; kk < 8; kk++) {
        ldmx4(qfh[kk][0], qfh[kk][1], qfh[kk][2], qfh[kk][3],
              s2u(&sQh[(wm + a_row) * FST + kk * 16 + a_col]));
        ldmx4(qfl[kk][0], qfl[kk][1], qfl[kk][2], qfl[kk][3],
              s2u(&sQl[(wm + a_row) * FST + kk * 16 + a_col]));
    }

    float o[16][4];
#pragma unroll
    for (int i = 0; i < 16; i++)
#pragma unroll
        for (int j = 0; j < 4; j++) o[i][j] = 0.f;
    float m0r = -1e30f, m1r = -1e30f, l0r = 0.f, l1r = 0.f;

    for (int jt = 0; jt < ntiles; jt++) {
        const int st = jt & 1;
        const int j0 = jt * 64;
        if (jt + 1 < ntiles) {
            F3_ISSUE(jt + 1);
            asm volatile("cp.async.wait_group 1;");
        } else {
            asm volatile("cp.async.wait_group 0;");
        }
        __syncthreads();

        const __nv_bfloat16* sKh = sKV + st * 4 * KVT;
        const __nv_bfloat16* sKl = sKh + KVT;
        const __nv_bfloat16* sVh = sKh + 2 * KVT;
        const __nv_bfloat16* sVl = sKh + 3 * KVT;

        float sa[8][4];
#pragma unroll
        for (int c = 0; c < 8; c++)
#pragma unroll
            for (int j = 0; j < 4; j++) sa[c][j] = 0.f;

#pragma unroll
        for (int kk = 0; kk < 8; kk++) {
#pragma unroll
            for (int njp = 0; njp < 4; njp++) {
                uint32_t bh0, bh1, bh2, bh3, bl0, bl1, bl2, bl3;
                ldmx4(bh0, bh1, bh2, bh3,
                      s2u(sKh + (njp * 16 + b_row) * FST + kk * 16 + b_col));
                ldmx4(bl0, bl1, bl2, bl3,
                      s2u(sKl + (njp * 16 + b_row) * FST + kk * 16 + b_col));
                mma16816(sa[2 * njp], qfh[kk][0], qfh[kk][1], qfh[kk][2], qfh[kk][3], bh0, bh1);
                mma16816(sa[2 * njp], qfh[kk][0], qfh[kk][1], qfh[kk][2], qfh[kk][3], bl0, bl1);
                mma16816(sa[2 * njp], qfl[kk][0], qfl[kk][1], qfl[kk][2], qfl[kk][3], bh0, bh1);
                mma16816(sa[2 * njp + 1], qfh[kk][0], qfh[kk][1], qfh[kk][2], qfh[kk][3], bh2, bh3);
                mma16816(sa[2 * njp + 1], qfh[kk][0], qfh[kk][1], qfh[kk][2], qfh[kk][3], bl2, bl3);
                mma16816(sa[2 * njp + 1], qfl[kk][0], qfl[kk][1], qfl[kk][2], qfl[kk][3], bh2, bh3);
            }
        }

        if (jt >= ntiles - 2) {
            const int qr0 = qb * 128 + wm + g;
            const int qr1 = qr0 + 8;
#pragma unroll
            for (int c = 0; c < 8; c++) {
                const int col = j0 + c * 8 + t2;
                if (col     > qr0) sa[c][0] = -1e30f;
                if (col + 1 > qr0) sa[c][1] = -1e30f;
                if (col     > qr1) sa[c][2] = -1e30f;
                if (col + 1 > qr1) sa[c][3] = -1e30f;
            }
        }

        float rm0 = -1e30f, rm1 = -1e30f;
#pragma unroll
        for (int c = 0; c < 8; c++) {
            rm0 = fmaxf(rm0, fmaxf(sa[c][0], sa[c][1]));
            rm1 = fmaxf(rm1, fmaxf(sa[c][2], sa[c][3]));
        }
        rm0 = fmaxf(rm0, __shfl_xor_sync(0xffffffffu, rm0, 1));
        rm0 = fmaxf(rm0, __shfl_xor_sync(0xffffffffu, rm0, 2));
        rm1 = fmaxf(rm1, __shfl_xor_sync(0xffffffffu, rm1, 1));
        rm1 = fmaxf(rm1, __shfl_xor_sync(0xffffffffu, rm1, 2));

        const float mn0 = fmaxf(m0r, rm0);
        const float mn1 = fmaxf(m1r, rm1);

        if (mn0 != m0r || mn1 != m1r) {
            const float al0 = exp2f(m0r - mn0);
            const float al1 = exp2f(m1r - mn1);
            l0r *= al0;
            l1r *= al1;
#pragma unroll
            for (int dj = 0; dj < 16; dj++) {
                o[dj][0] *= al0;
                o[dj][1] *= al0;
                o[dj][2] *= al1;
                o[dj][3] *= al1;
            }
            m0r = mn0;
            m1r = mn1;
        }

        float rs0 = 0.f, rs1 = 0.f;
#pragma unroll
        for (int c = 0; c < 8; c++) {
            sa[c][0] = exp2f(sa[c][0] - m0r);
            sa[c][1] = exp2f(sa[c][1] - m0r);
            sa[c][2] = exp2f(sa[c][2] - m1r);
            sa[c][3] = exp2f(sa[c][3] - m1r);
            rs0 += sa[c][0] + sa[c][1];
            rs1 += sa[c][2] + sa[c][3];
        }
        rs0 += __shfl_xor_sync(0xffffffffu, rs0, 1);
        rs0 += __shfl_xor_sync(0xffffffffu, rs0, 2);
        rs1 += __shfl_xor_sync(0xffffffffu, rs1, 1);
        rs1 += __shfl_xor_sync(0xffffffffu, rs1, 2);

        l0r += rs0;
        l1r += rs1;

#pragma unroll
        for (int ks = 0; ks < 4; ks++) {
            const int c0 = 2 * ks, c1 = 2 * ks + 1;
            uint32_t pl0, pl1, pl2, pl3;
            const uint32_t ph0 = pack_hl(sa[c0][0], sa[c0][1], pl0);
            const uint32_t ph1 = pack_hl(sa[c0][2], sa[c0][3], pl1);
            const uint32_t ph2 = pack_hl(sa[c1][0], sa[c1][1], pl2);
            const uint32_t ph3 = pack_hl(sa[c1][2], sa[c1][3], pl3);
#pragma unroll
            for (int djp = 0; djp < 8; djp++) {
                uint32_t vh0, vh1, vh2, vh3, vl0, vl1, vl2, vl3;
                ldmx4t(vh0, vh1, vh2, vh3,
                       s2u(sVh + (ks * 16 + v_row) * FST + djp * 16 + v_col));
                ldmx4t(vl0, vl1, vl2, vl3,
                       s2u(sVl + (ks * 16 + v_row) * FST + djp * 16 + v_col));
                mma16816(o[2 * djp], ph0, ph1, ph2, ph3, vh0, vh1);
                mma16816(o[2 * djp], ph0, ph1, ph2, ph3, vl0, vl1);
                mma16816(o[2 * djp], pl0, pl1, pl2, pl3, vh0, vh1);
                mma16816(o[2 * djp + 1], ph0, ph1, ph2, ph3, vh2, vh3);
                mma16816(o[2 * djp + 1], ph0, ph1, ph2, ph3, vl2, vl3);
                mma16816(o[2 * djp + 1], pl0, pl1, pl2, pl3, vh2, vh3);
            }
        }
        __syncthreads();
    }
#undef F3_ISSUE

    // epilogue: normalize + hi/lo split directly to bf16
    const float inv0 = 1.0f / l0r;
    const float inv1 = 1.0f / l1r;
    const int row0 = qb * 128 + wm + g;
    const int row1 = row0 + 8;
#pragma unroll
    for (int dj = 0; dj < 16; dj++) {
        uint32_t lo;
        uint32_t hi = pack_hl(o[dj][0] * inv0, o[dj][1] * inv0, lo);
        const size_t b0 = (size_t)row0 * D_MODEL + h * HD + dj * 8 + t2;
        *(uint32_t*)(AOh + b0) = hi;
        *(uint32_t*)(AOl + b0) = lo;
        hi = pack_hl(o[dj][2] * inv1, o[dj][3] * inv1, lo);
        const size_t b1 = (size_t)row1 * D_MODEL + h * HD + dj * 8 + t2;
        *(uint32_t*)(AOh + b1) = hi;
        *(uint32_t*)(AOl + b1) = lo;
    }
}

// ---------------------------------------------------------------------------
// launch — signature order: x, wq, wk, wv, wo
// ---------------------------------------------------------------------------
extern "C" void kernel_launch(void* const* d_in, const int* in_sizes, int n_in,
                              void* d_out, int out_size)
{
    const float* x  = (const float*)d_in[0];
    const float* wq = (const float*)d_in[1];
    const float* wk = (const float*)d_in[2];
    const float* wv = (const float*)d_in[3];
    const float* wo = (const float*)d_in[4];
    float* out = (float*)d_out;

    __nv_bfloat16 *xh, *xl, *aoh, *aol, *wqh, *wql, *wkvh, *wkvl, *woh, *wol;
    __nv_bfloat16 *qhh, *qll, *kvh, *kvl;
    float *ct, *st;
    cudaGetSymbolAddress((void**)&xh,   g_xh);   cudaGetSymbolAddress((void**)&xl,   g_xl);
    cudaGetSymbolAddress((void**)&aoh,  g_aoh);  cudaGetSymbolAddress((void**)&aol,  g_aol);
    cudaGetSymbolAddress((void**)&wqh,  g_wqh);  cudaGetSymbolAddress((void**)&wql,  g_wql);
    cudaGetSymbolAddress((void**)&wkvh, g_wkvh); cudaGetSymbolAddress((void**)&wkvl, g_wkvl);
    cudaGetSymbolAddress((void**)&woh,  g_woh);  cudaGetSymbolAddress((void**)&wol,  g_wol);
    cudaGetSymbolAddress((void**)&qhh,  g_Qh);   cudaGetSymbolAddress((void**)&qll,  g_Ql);
    cudaGetSymbolAddress((void**)&kvh,  g_KVh);  cudaGetSymbolAddress((void**)&kvl,  g_KVl);
    cudaGetSymbolAddress((void**)&ct,   g_ct);   cudaGetSymbolAddress((void**)&st,   g_st);

    cudaFuncSetAttribute(gemm_pipe<0>, cudaFuncAttributeMaxDynamicSharedMemorySize, GP_SMEM);
    cudaFuncSetAttribute(gemm_pipe<1>, cudaFuncAttributeMaxDynamicSharedMemorySize, GP_SMEM);
    cudaFuncSetAttribute(flash3, cudaFuncAttributeMaxDynamicSharedMemorySize, F3_SMEM);

    // rope tables + conversions
    rope_tab<<<T_SEQ, 64>>>(ct, st);
    conv_hilo8<<<SZ_X / 2048, 256>>>(x, xh, xl, SZ_X);
    conv_t_all<<<dim3(320, 128), dim3(32, 8)>>>(wq, wk, wv, wo,
                                                wqh, wql, wkvh, wkvl, woh, wol);

    // Q projection: fused rope + scale + split (scale includes log2e)
    gemm_pipe<1><<<dim3(D_MODEL / 128, T_SEQ / 128), 256, GP_SMEM>>>(
        xh, xl, wqh, wql, nullptr, qhh, qll, ct, st,
        T_SEQ, D_MODEL, D_MODEL, D_MODEL, SCALE * LOG2E, D_MODEL);

    // KV projection: fused rope (K only) + split
    gemm_pipe<1><<<dim3(KV2 / 128, T_SEQ / 128), 256, GP_SMEM>>>(
        xh, xl, wkvh, wkvl, nullptr, kvh, kvl, ct, st,
        T_SEQ, KV2, D_MODEL, KV2, 1.0f, KV_DIM);

    // attention (heavy-first, exp2 softmax, Q-in-registers)
    flash3<<<dim3(NB, N_HEADS), 256, F3_SMEM>>>(qhh, qll, kvh, kvl, aoh, aol);

    // output projection (fp32 out)
    gemm_pipe<0><<<dim3(D_MODEL / 128, T_SEQ / 128), 256, GP_SMEM>>>(
        aoh, aol, woh, wol, out, nullptr, nullptr, nullptr, nullptr,
        T_SEQ, D_MODEL, D_MODEL, 0, 1.0f, 0);
}